// round 13
// baseline (speedup 1.0000x reference)
#include <cuda_runtime.h>
#include <cuda_bf16.h>
#include <cuda_fp16.h>

#define SEQ   40
#define INC   24
#define NK    36
#define FLAT  1440
#define HID   64
#define STEPS 50

__device__ float g_theta0[HID * 65536];   // [dim][sample], fp32

__device__ __forceinline__ float tanhap(float x) {
    float r; asm("tanh.approx.f32 %0,%1;" : "=f"(r) : "f"(x)); return r;
}
__device__ __forceinline__ unsigned f2tf(float f) {
    unsigned u; asm("cvt.rna.tf32.f32 %0,%1;" : "=r"(u) : "f"(f)); return u;
}
__device__ __forceinline__ void mma_tf32(
    float (&c)[4], const unsigned (&a)[4], unsigned b0, unsigned b1)
{
    asm("mma.sync.aligned.m16n8k8.row.col.f32.tf32.tf32.f32 "
        "{%0,%1,%2,%3},{%4,%5,%6,%7},{%8,%9},{%0,%1,%2,%3};"
        : "+f"(c[0]), "+f"(c[1]), "+f"(c[2]), "+f"(c[3])
        : "r"(a[0]), "r"(a[1]), "r"(a[2]), "r"(a[3]), "r"(b0), "r"(b1));
}
__device__ __forceinline__ void mma_fp16(
    float (&c)[4], const unsigned (&a)[4], unsigned b0, unsigned b1)
{
    asm("mma.sync.aligned.m16n8k16.row.col.f32.f16.f16.f32 "
        "{%0,%1,%2,%3},{%4,%5,%6,%7},{%8,%9},{%0,%1,%2,%3};"
        : "+f"(c[0]), "+f"(c[1]), "+f"(c[2]), "+f"(c[3])
        : "r"(a[0]), "r"(a[1]), "r"(a[2]), "r"(a[3]), "r"(b0), "r"(b1));
}
__device__ __forceinline__ unsigned pkh2(float a, float b) {
    __half2 h = __floats2half2_rn(a, b);
    return *reinterpret_cast<unsigned*>(&h);
}
__device__ __forceinline__ float2 u2f2(unsigned u) {
    return __half22float2(*reinterpret_cast<__half2*>(&u));
}

// ============================== Encoder (unchanged) =========================
#define ENC_SPB 32
#define SCST    1444
#define SWST    36
#define SH1ST   132
#define NCHUNK  (FLAT / 32)
#define ENC_SMEM_BYTES ((ENC_SPB*SCST + 2*128*SWST) * 4)

__global__ void __launch_bounds__(256) enc_kernel(
    const float* __restrict__ x,
    const float* __restrict__ conv_w, const float* __restrict__ conv_b,
    const float* __restrict__ enc1_w, const float* __restrict__ enc1_b,
    const float* __restrict__ enc2_w, const float* __restrict__ enc2_b,
    int B)
{
    extern __shared__ unsigned smu[];
    unsigned* sC  = smu;
    unsigned* sW0 = sC + ENC_SPB * SCST;
    unsigned* sW1 = sW0 + 128 * SWST;
    float*    sH1 = (float*)sC;

    const int tid = threadIdx.x;
    const long long blk = blockIdx.x;

    float* scw = (float*)sW0;
    for (int i = tid; i < NK * 72; i += 256) scw[i] = conv_w[i];
    __syncthreads();

    {
        const int sp = tid >> 3;
        const int sq = tid & 7;
        const float* xs = x + (blk * ENC_SPB + sp) * (SEQ * INC);
        float* sCf = (float*)sC;
#pragma unroll
        for (int ch = 0; ch < 2; ch++) {
            const int c0 = ch * 12;
            float xr[7][12];
#pragma unroll
            for (int r = 0; r < 7; r++) {
                const int s = sq * 5 - 1 + r;
                if (s >= 0 && s < SEQ) {
                    const float4 v0 = __ldg((const float4*)(xs + s * INC + c0));
                    const float4 v1 = __ldg((const float4*)(xs + s * INC + c0 + 4));
                    const float4 v2 = __ldg((const float4*)(xs + s * INC + c0 + 8));
                    xr[r][0]=v0.x; xr[r][1]=v0.y; xr[r][2]=v0.z; xr[r][3]=v0.w;
                    xr[r][4]=v1.x; xr[r][5]=v1.y; xr[r][6]=v1.z; xr[r][7]=v1.w;
                    xr[r][8]=v2.x; xr[r][9]=v2.y; xr[r][10]=v2.z; xr[r][11]=v2.w;
                } else {
#pragma unroll
                    for (int cc = 0; cc < 12; cc++) xr[r][cc] = 0.0f;
                }
            }
            for (int k = 0; k < NK; k++) {
                float acc[5];
                if (ch == 0) {
                    const float bk = __ldg(&conv_b[k]);
#pragma unroll
                    for (int i = 0; i < 5; i++) acc[i] = bk;
                } else {
#pragma unroll
                    for (int i = 0; i < 5; i++)
                        acc[i] = sCf[sp * SCST + k * SEQ + sq * 5 + i];
                }
#pragma unroll
                for (int cc = 0; cc < 12; cc++) {
                    const float w0 = scw[k * 72 + (c0 + cc) * 3 + 0];
                    const float w1 = scw[k * 72 + (c0 + cc) * 3 + 1];
                    const float w2 = scw[k * 72 + (c0 + cc) * 3 + 2];
#pragma unroll
                    for (int i = 0; i < 5; i++) {
                        acc[i] = fmaf(w0, xr[i][cc],     acc[i]);
                        acc[i] = fmaf(w1, xr[i + 1][cc], acc[i]);
                        acc[i] = fmaf(w2, xr[i + 2][cc], acc[i]);
                    }
                }
                if (ch == 0) {
#pragma unroll
                    for (int i = 0; i < 5; i++)
                        sCf[sp * SCST + k * SEQ + sq * 5 + i] = acc[i];
                } else {
#pragma unroll
                    for (int i = 0; i < 5; i++) {
                        const float v  = acc[i];
                        const float sg = fmaf(0.5f, tanhap(0.5f * v), 0.5f);
                        sC[sp * SCST + k * SEQ + sq * 5 + i] = f2tf(v * sg);
                    }
                }
            }
        }
    }
    __syncthreads();

    const int w    = tid >> 5;
    const int lane = tid & 31;
    const int g    = lane >> 2;
    const int tig  = lane & 3;
    const int mh   = w & 1;
    const int nq   = w >> 1;
    const int srow = mh * 16 + g;
    const int nbase = nq * 32;

    float c[4][4];
#pragma unroll
    for (int nt = 0; nt < 4; nt++) {
        const int n0 = nbase + nt * 8 + 2 * tig;
        c[nt][0] = __ldg(&enc1_b[n0]);
        c[nt][1] = __ldg(&enc1_b[n0 + 1]);
        c[nt][2] = c[nt][0];
        c[nt][3] = c[nt][1];
    }

    float4 pre[4];
#pragma unroll
    for (int j = 0; j < 4; j++) {
        const int f  = tid + j * 256;
        const int oc = f >> 3, qd = f & 7;
        pre[j] = __ldg((const float4*)(enc1_w + (size_t)oc * FLAT + qd * 4));
    }

    for (int kci = 0; kci < NCHUNK; kci++) {
        unsigned* buf = (kci & 1) ? sW1 : sW0;
#pragma unroll
        for (int j = 0; j < 4; j++) {
            const int f  = tid + j * 256;
            const int oc = f >> 3, qd = f & 7;
            uint4 u;
            u.x = f2tf(pre[j].x); u.y = f2tf(pre[j].y);
            u.z = f2tf(pre[j].z); u.w = f2tf(pre[j].w);
            *(uint4*)(buf + oc * SWST + qd * 4) = u;
        }
        if (kci + 1 < NCHUNK) {
            const int kc = (kci + 1) * 32;
#pragma unroll
            for (int j = 0; j < 4; j++) {
                const int f  = tid + j * 256;
                const int oc = f >> 3, qd = f & 7;
                pre[j] = __ldg((const float4*)(enc1_w + (size_t)oc * FLAT + kc + qd * 4));
            }
        }
        __syncthreads();
        const int kc = kci * 32;
#pragma unroll
        for (int kt = 0; kt < 4; kt++) {
            unsigned a[4];
            const unsigned* ar = sC + srow * SCST + kc + kt * 8 + tig;
            a[0] = ar[0];
            a[1] = ar[8 * SCST];
            a[2] = ar[4];
            a[3] = ar[8 * SCST + 4];
#pragma unroll
            for (int nt = 0; nt < 4; nt++) {
                const unsigned* br = buf + (nbase + nt * 8 + g) * SWST + kt * 8 + tig;
                mma_tf32(c[nt], a, br[0], br[4]);
            }
        }
    }
    __syncthreads();

#pragma unroll
    for (int nt = 0; nt < 4; nt++) {
        const int n0 = nbase + nt * 8 + 2 * tig;
        sH1[srow * SH1ST + n0]           = fmaxf(c[nt][0], 0.0f);
        sH1[srow * SH1ST + n0 + 1]       = fmaxf(c[nt][1], 0.0f);
        sH1[(srow + 8) * SH1ST + n0]     = fmaxf(c[nt][2], 0.0f);
        sH1[(srow + 8) * SH1ST + n0 + 1] = fmaxf(c[nt][3], 0.0f);
    }
    __syncthreads();

    for (int t = tid; t < ENC_SPB * HID; t += 256) {
        const int oc = t >> 5;
        const int sp = t & 31;
        float acc = __ldg(&enc2_b[oc]);
        const float* wr = enc2_w + oc * 128;
        const float* hv = sH1 + sp * SH1ST;
#pragma unroll
        for (int i = 0; i < 128; i += 4) {
            const float4 wv = __ldg((const float4*)(wr + i));
            const float4 h4 = *(const float4*)(hv + i);
            acc = fmaf(wv.x, h4.x, fmaf(wv.y, h4.y, fmaf(wv.z, h4.z, fmaf(wv.w, h4.w, acc))));
        }
        g_theta0[(size_t)oc * B + blk * ENC_SPB + sp] = acc;
    }
}

// ================================ ODE ======================================
// Warp-autonomous: 128 thr / 4 warps / 64 samples per CTA.  Warp owns 16
// samples x full 64-dim state; samples on M, dims on N/K.  W1/W2 = fp16
// B-frags in registers.  C-frag of gemm == A-frag of next gemm (same thread).
// k1..k5 spill to THREAD-PRIVATE smem (no barriers in the loop).
#define KPW  576            // words per k-buffer per warp (16 rows * 36)
#define WRPW (5 * KPW)

// one f eval fully in registers: A (stage input) -> C (= k)
__device__ __forceinline__ void eval_f_reg(
    const unsigned (&W1B)[4][8][2], const unsigned (&W2B)[4][8][2],
    const unsigned (&b1p)[8], const unsigned (&b2p)[8],
    const unsigned (&A)[8][2], float (&C)[8][4])
{
    float H[8][4];
#pragma unroll
    for (int nt = 0; nt < 8; nt++) {
        const float2 b = u2f2(b1p[nt]);
        H[nt][0] = b.x; H[nt][1] = b.y; H[nt][2] = b.x; H[nt][3] = b.y;
    }
#pragma unroll
    for (int kt = 0; kt < 4; kt++) {
        const unsigned a[4] = {A[2*kt][0], A[2*kt][1], A[2*kt+1][0], A[2*kt+1][1]};
#pragma unroll
        for (int nt = 0; nt < 8; nt++)
            mma_fp16(H[nt], a, W1B[kt][nt][0], W1B[kt][nt][1]);
    }
    unsigned A2[8][2];
#pragma unroll
    for (int nt = 0; nt < 8; nt++) {
        A2[nt][0] = pkh2(tanhap(H[nt][0]), tanhap(H[nt][1]));
        A2[nt][1] = pkh2(tanhap(H[nt][2]), tanhap(H[nt][3]));
    }
#pragma unroll
    for (int nt = 0; nt < 8; nt++) {
        const float2 b = u2f2(b2p[nt]);
        C[nt][0] = b.x; C[nt][1] = b.y; C[nt][2] = b.x; C[nt][3] = b.y;
    }
#pragma unroll
    for (int kt = 0; kt < 4; kt++) {
        const unsigned a[4] = {A2[2*kt][0], A2[2*kt][1], A2[2*kt+1][0], A2[2*kt+1][1]};
#pragma unroll
        for (int nt = 0; nt < 8; nt++)
            mma_fp16(C[nt], a, W2B[kt][nt][0], W2B[kt][nt][1]);
    }
}

__global__ void __launch_bounds__(128, 2) ode_kernel(
    const float* __restrict__ t_span,
    const float* __restrict__ w1g, const float* __restrict__ b1g,
    const float* __restrict__ w2g, const float* __restrict__ b2g,
    const float* __restrict__ r1w, const float* __restrict__ r1b,
    const float* __restrict__ r2w, const float* __restrict__ r2b,
    float* __restrict__ out, int B)
{
    __shared__ unsigned sk[4 * WRPW];          // 46080 B

    const int tid  = threadIdx.x;
    const int w    = tid >> 5;
    const int lane = tid & 31;
    const int g    = lane >> 2;
    const int tig  = lane & 3;

    unsigned* kb  = sk + w * WRPW;
    unsigned* kb1 = kb;
    unsigned* kb2 = kb + KPW;
    unsigned* kb3 = kb + 2 * KPW;
    unsigned* kb4 = kb + 3 * KPW;
    unsigned* kb5 = kb + 4 * KPW;
    const int r0 = g * 36 + tig;               // row g slot base
    const int r1 = (g + 8) * 36 + tig;         // row g+8 slot base

    // W1/W2 as fp16 B-fragments
    unsigned W1B[4][8][2], W2B[4][8][2];
#pragma unroll
    for (int kt = 0; kt < 4; kt++)
#pragma unroll
        for (int nt = 0; nt < 8; nt++) {
            const int n  = nt * 8 + g;
            const int k0 = kt * 16 + 2 * tig;
            W1B[kt][nt][0] = pkh2(__ldg(&w1g[n*HID+k0]),   __ldg(&w1g[n*HID+k0+1]));
            W1B[kt][nt][1] = pkh2(__ldg(&w1g[n*HID+k0+8]), __ldg(&w1g[n*HID+k0+9]));
            W2B[kt][nt][0] = pkh2(__ldg(&w2g[n*HID+k0]),   __ldg(&w2g[n*HID+k0+1]));
            W2B[kt][nt][1] = pkh2(__ldg(&w2g[n*HID+k0+8]), __ldg(&w2g[n*HID+k0+9]));
        }
    unsigned b1p[8], b2p[8];
#pragma unroll
    for (int nt = 0; nt < 8; nt++) {
        const int n = nt * 8 + 2 * tig;
        b1p[nt] = pkh2(__ldg(&b1g[n]), __ldg(&b1g[n + 1]));
        b2p[nt] = pkh2(__ldg(&b2g[n]), __ldg(&b2g[n + 1]));
    }

    const float dt = (__ldg(&t_span[1]) - __ldg(&t_span[0])) * (1.0f / STEPS);

    const long long s0 = (long long)blockIdx.x * 64 + w * 16 + g;
    float y[8][4];
#pragma unroll
    for (int nt = 0; nt < 8; nt++) {
        const int d = nt * 8 + 2 * tig;
        y[nt][0] = __ldg(&g_theta0[(size_t)d       * B + s0]);
        y[nt][1] = __ldg(&g_theta0[(size_t)(d + 1) * B + s0]);
        y[nt][2] = __ldg(&g_theta0[(size_t)d       * B + s0 + 8]);
        y[nt][3] = __ldg(&g_theta0[(size_t)(d + 1) * B + s0 + 8]);
    }

    unsigned A[8][2];
    float C[8][4];

#define STORE_K(kbx)                                                           \
    _Pragma("unroll") for (int nt = 0; nt < 8; nt++) {                         \
        (kbx)[r0 + nt * 4] = pkh2(C[nt][0], C[nt][1]);                         \
        (kbx)[r1 + nt * 4] = pkh2(C[nt][2], C[nt][3]);                         \
    }
// accumulate c * k (fp16 pair at kbx[off]) into (ax, ay)
#define KADD(kbx, cc, off) { const float2 t_ = u2f2((kbx)[off]);               \
        ax = fmaf(cc, t_.x, ax); ay = fmaf(cc, t_.y, ay); }

    for (int step = 0; step < STEPS; step++) {
        // stage 1: A = fp16(y)
#pragma unroll
        for (int nt = 0; nt < 8; nt++) {
            A[nt][0] = pkh2(y[nt][0], y[nt][1]);
            A[nt][1] = pkh2(y[nt][2], y[nt][3]);
        }
        eval_f_reg(W1B, W2B, b1p, b2p, A, C);
        STORE_K(kb1);
        {   // stage 2
            const float c1 = dt * 0.2f;
#pragma unroll
            for (int nt = 0; nt < 8; nt++) {
                const int o0 = r0 + nt * 4, o1 = r1 + nt * 4;
                float ax = y[nt][0], ay = y[nt][1];
                KADD(kb1, c1, o0);
                A[nt][0] = pkh2(ax, ay);
                ax = y[nt][2]; ay = y[nt][3];
                KADD(kb1, c1, o1);
                A[nt][1] = pkh2(ax, ay);
            }
        }
        eval_f_reg(W1B, W2B, b1p, b2p, A, C);
        STORE_K(kb2);
        {   // stage 3
            const float c1 = dt * (3.0f/40.0f), c2 = dt * (9.0f/40.0f);
#pragma unroll
            for (int nt = 0; nt < 8; nt++) {
                const int o0 = r0 + nt * 4, o1 = r1 + nt * 4;
                float ax = y[nt][0], ay = y[nt][1];
                KADD(kb1, c1, o0); KADD(kb2, c2, o0);
                A[nt][0] = pkh2(ax, ay);
                ax = y[nt][2]; ay = y[nt][3];
                KADD(kb1, c1, o1); KADD(kb2, c2, o1);
                A[nt][1] = pkh2(ax, ay);
            }
        }
        eval_f_reg(W1B, W2B, b1p, b2p, A, C);
        STORE_K(kb3);
        {   // stage 4
            const float c1 = dt * (44.0f/45.0f), c2 = dt * (-56.0f/15.0f),
                        c3 = dt * (32.0f/9.0f);
#pragma unroll
            for (int nt = 0; nt < 8; nt++) {
                const int o0 = r0 + nt * 4, o1 = r1 + nt * 4;
                float ax = y[nt][0], ay = y[nt][1];
                KADD(kb1, c1, o0); KADD(kb2, c2, o0); KADD(kb3, c3, o0);
                A[nt][0] = pkh2(ax, ay);
                ax = y[nt][2]; ay = y[nt][3];
                KADD(kb1, c1, o1); KADD(kb2, c2, o1); KADD(kb3, c3, o1);
                A[nt][1] = pkh2(ax, ay);
            }
        }
        eval_f_reg(W1B, W2B, b1p, b2p, A, C);
        STORE_K(kb4);
        {   // stage 5
            const float c1 = dt * (19372.0f/6561.0f), c2 = dt * (-25360.0f/2187.0f),
                        c3 = dt * (64448.0f/6561.0f), c4 = dt * (-212.0f/729.0f);
#pragma unroll
            for (int nt = 0; nt < 8; nt++) {
                const int o0 = r0 + nt * 4, o1 = r1 + nt * 4;
                float ax = y[nt][0], ay = y[nt][1];
                KADD(kb1, c1, o0); KADD(kb2, c2, o0); KADD(kb3, c3, o0); KADD(kb4, c4, o0);
                A[nt][0] = pkh2(ax, ay);
                ax = y[nt][2]; ay = y[nt][3];
                KADD(kb1, c1, o1); KADD(kb2, c2, o1); KADD(kb3, c3, o1); KADD(kb4, c4, o1);
                A[nt][1] = pkh2(ax, ay);
            }
        }
        eval_f_reg(W1B, W2B, b1p, b2p, A, C);
        STORE_K(kb5);
        {   // stage 6
            const float c1 = dt * (9017.0f/3168.0f), c2 = dt * (-355.0f/33.0f),
                        c3 = dt * (46732.0f/5247.0f), c4 = dt * (49.0f/176.0f),
                        c5 = dt * (-5103.0f/18656.0f);
#pragma unroll
            for (int nt = 0; nt < 8; nt++) {
                const int o0 = r0 + nt * 4, o1 = r1 + nt * 4;
                float ax = y[nt][0], ay = y[nt][1];
                KADD(kb1, c1, o0); KADD(kb2, c2, o0); KADD(kb3, c3, o0);
                KADD(kb4, c4, o0); KADD(kb5, c5, o0);
                A[nt][0] = pkh2(ax, ay);
                ax = y[nt][2]; ay = y[nt][3];
                KADD(kb1, c1, o1); KADD(kb2, c2, o1); KADD(kb3, c3, o1);
                KADD(kb4, c4, o1); KADD(kb5, c5, o1);
                A[nt][1] = pkh2(ax, ay);
            }
        }
        eval_f_reg(W1B, W2B, b1p, b2p, A, C);   // C = k6
        {   // final: y += dt*(b1 k1 + b3 k3 + b4 k4 + b5 k5 + b6 k6)  (fp32)
            const float d1 = dt * (35.0f/384.0f),  d3 = dt * (500.0f/1113.0f),
                        d4 = dt * (125.0f/192.0f), d5 = dt * (-2187.0f/6784.0f),
                        d6 = dt * (11.0f/84.0f);
#pragma unroll
            for (int nt = 0; nt < 8; nt++) {
                const int o0 = r0 + nt * 4, o1 = r1 + nt * 4;
                {
                    float ax = fmaf(d6, C[nt][0], y[nt][0]);
                    float ay = fmaf(d6, C[nt][1], y[nt][1]);
                    KADD(kb1, d1, o0); KADD(kb3, d3, o0);
                    KADD(kb4, d4, o0); KADD(kb5, d5, o0);
                    y[nt][0] = ax; y[nt][1] = ay;
                }
                {
                    float ax = fmaf(d6, C[nt][2], y[nt][2]);
                    float ay = fmaf(d6, C[nt][3], y[nt][3]);
                    KADD(kb1, d1, o1); KADD(kb3, d3, o1);
                    KADD(kb4, d4, o1); KADD(kb5, d5, o1);
                    y[nt][2] = ax; y[nt][3] = ay;
                }
            }
        }
    }

    // ---- stage y (fp32) into smem [64 samples][68] for the regressor ----
    __syncthreads();                 // all warps finished with their k-buffers
    float* sYf = (float*)sk;         // 64*68*4 = 17408 B <= 46080 B
    {
        const int sr = w * 16 + g;
#pragma unroll
        for (int nt = 0; nt < 8; nt++) {
            const int d = nt * 8 + 2 * tig;
            sYf[sr * 68 + d]           = y[nt][0];
            sYf[sr * 68 + d + 1]       = y[nt][1];
            sYf[(sr + 8) * 68 + d]     = y[nt][2];
            sYf[(sr + 8) * 68 + d + 1] = y[nt][3];
        }
    }
    __syncthreads();

    // ---- regressor: 2 threads per sample, 16 reg1 rows each ----
    {
        const int s  = tid >> 1;
        const int mg = (tid & 1) * 16;
        float accm[16];
#pragma unroll
        for (int m = 0; m < 16; m++) accm[m] = __ldg(&r1b[mg + m]);
        for (int i = 0; i < HID; i++) {
            const float yy = sYf[s * 68 + i];
#pragma unroll
            for (int m = 0; m < 16; m++)
                accm[m] = fmaf(__ldg(&r1w[(mg + m) * HID + i]), yy, accm[m]);
        }
        float part = 0.0f;
#pragma unroll
        for (int m = 0; m < 16; m++)
            part = fmaf(__ldg(&r2w[mg + m]), fmaxf(accm[m], 0.0f), part);
        part += __shfl_xor_sync(0xffffffffu, part, 1);
        if ((tid & 1) == 0)
            out[(long long)blockIdx.x * 64 + s] = part + __ldg(&r2b[0]);
    }
}

// ============================== launch ======================================
extern "C" void kernel_launch(void* const* d_in, const int* in_sizes, int n_in,
                              void* d_out, int out_size)
{
    const float* x      = (const float*)d_in[0];
    const float* t_span = (const float*)d_in[1];
    const float* conv_w = (const float*)d_in[2];
    const float* conv_b = (const float*)d_in[3];
    const float* enc1_w = (const float*)d_in[4];
    const float* enc1_b = (const float*)d_in[5];
    const float* enc2_w = (const float*)d_in[6];
    const float* enc2_b = (const float*)d_in[7];
    const float* ode1_w = (const float*)d_in[8];
    const float* ode1_b = (const float*)d_in[9];
    const float* ode2_w = (const float*)d_in[10];
    const float* ode2_b = (const float*)d_in[11];
    const float* reg1_w = (const float*)d_in[12];
    const float* reg1_b = (const float*)d_in[13];
    const float* reg2_w = (const float*)d_in[14];
    const float* reg2_b = (const float*)d_in[15];
    float* out = (float*)d_out;

    const int B = in_sizes[0] / (SEQ * INC);

    cudaFuncSetAttribute(enc_kernel, cudaFuncAttributeMaxDynamicSharedMemorySize,
                         ENC_SMEM_BYTES);

    enc_kernel<<<B / ENC_SPB, 256, ENC_SMEM_BYTES>>>(
        x, conv_w, conv_b, enc1_w, enc1_b, enc2_w, enc2_b, B);
    ode_kernel<<<B / 64, 128>>>(
        t_span, ode1_w, ode1_b, ode2_w, ode2_b,
        reg1_w, reg1_b, reg2_w, reg2_b, out, B);
}

// round 14
// speedup vs baseline: 1.3740x; 1.3740x over previous
#include <cuda_runtime.h>
#include <cuda_bf16.h>
#include <cuda_fp16.h>

// ---------------------------------------------------------------------------
// CNN_ODE: conv1d+SiLU -> MLP encoder (tf32 mma, double-buffered) -> 50-step
// fixed dopri5 (64-dim neural ODE, fp16 m16n8k16 mma, 16-sample CTAs) ->
// regressor.  B = 65536.
// ---------------------------------------------------------------------------

#define SEQ   40
#define INC   24
#define NK    36
#define FLAT  1440
#define HID   64
#define STEPS 50

// theta0 scratch, TRANSPOSED: [dim][sample], float
__device__ float g_theta0[HID * 65536];   // 16 MB

__device__ __forceinline__ float tanhap(float x) {
    float r; asm("tanh.approx.f32 %0,%1;" : "=f"(r) : "f"(x)); return r;
}
__device__ __forceinline__ unsigned f2tf(float f) {
    unsigned u; asm("cvt.rna.tf32.f32 %0,%1;" : "=r"(u) : "f"(f)); return u;
}
__device__ __forceinline__ void mma_tf32(
    float (&c)[4], const unsigned (&a)[4], unsigned b0, unsigned b1)
{
    asm("mma.sync.aligned.m16n8k8.row.col.f32.tf32.tf32.f32 "
        "{%0,%1,%2,%3},{%4,%5,%6,%7},{%8,%9},{%0,%1,%2,%3};"
        : "+f"(c[0]), "+f"(c[1]), "+f"(c[2]), "+f"(c[3])
        : "r"(a[0]), "r"(a[1]), "r"(a[2]), "r"(a[3]), "r"(b0), "r"(b1));
}
__device__ __forceinline__ void mma_fp16(
    float (&c)[4], const unsigned (&a)[4], unsigned b0, unsigned b1)
{
    asm("mma.sync.aligned.m16n8k16.row.col.f32.f16.f16.f32 "
        "{%0,%1,%2,%3},{%4,%5,%6,%7},{%8,%9},{%0,%1,%2,%3};"
        : "+f"(c[0]), "+f"(c[1]), "+f"(c[2]), "+f"(c[3])
        : "r"(a[0]), "r"(a[1]), "r"(a[2]), "r"(a[3]), "r"(b0), "r"(b1));
}
__device__ __forceinline__ unsigned pkh2(float a, float b) {
    __half2 h = __floats2half2_rn(a, b);
    return *reinterpret_cast<unsigned*>(&h);
}

// ============================== Encoder (unchanged) =========================
#define ENC_SPB 32
#define SCST    1444
#define SWST    36
#define SH1ST   132
#define NCHUNK  (FLAT / 32)
#define ENC_SMEM_BYTES ((ENC_SPB*SCST + 2*128*SWST) * 4)

__global__ void __launch_bounds__(256) enc_kernel(
    const float* __restrict__ x,
    const float* __restrict__ conv_w, const float* __restrict__ conv_b,
    const float* __restrict__ enc1_w, const float* __restrict__ enc1_b,
    const float* __restrict__ enc2_w, const float* __restrict__ enc2_b,
    int B)
{
    extern __shared__ unsigned smu[];
    unsigned* sC  = smu;
    unsigned* sW0 = sC + ENC_SPB * SCST;
    unsigned* sW1 = sW0 + 128 * SWST;
    float*    sH1 = (float*)sC;

    const int tid = threadIdx.x;
    const long long blk = blockIdx.x;

    float* scw = (float*)sW0;
    for (int i = tid; i < NK * 72; i += 256) scw[i] = conv_w[i];
    __syncthreads();

    {
        const int sp = tid >> 3;
        const int sq = tid & 7;
        const float* xs = x + (blk * ENC_SPB + sp) * (SEQ * INC);
        float* sCf = (float*)sC;
#pragma unroll
        for (int ch = 0; ch < 2; ch++) {
            const int c0 = ch * 12;
            float xr[7][12];
#pragma unroll
            for (int r = 0; r < 7; r++) {
                const int s = sq * 5 - 1 + r;
                if (s >= 0 && s < SEQ) {
                    const float4 v0 = __ldg((const float4*)(xs + s * INC + c0));
                    const float4 v1 = __ldg((const float4*)(xs + s * INC + c0 + 4));
                    const float4 v2 = __ldg((const float4*)(xs + s * INC + c0 + 8));
                    xr[r][0]=v0.x; xr[r][1]=v0.y; xr[r][2]=v0.z; xr[r][3]=v0.w;
                    xr[r][4]=v1.x; xr[r][5]=v1.y; xr[r][6]=v1.z; xr[r][7]=v1.w;
                    xr[r][8]=v2.x; xr[r][9]=v2.y; xr[r][10]=v2.z; xr[r][11]=v2.w;
                } else {
#pragma unroll
                    for (int cc = 0; cc < 12; cc++) xr[r][cc] = 0.0f;
                }
            }
            for (int k = 0; k < NK; k++) {
                float acc[5];
                if (ch == 0) {
                    const float bk = __ldg(&conv_b[k]);
#pragma unroll
                    for (int i = 0; i < 5; i++) acc[i] = bk;
                } else {
#pragma unroll
                    for (int i = 0; i < 5; i++)
                        acc[i] = sCf[sp * SCST + k * SEQ + sq * 5 + i];
                }
#pragma unroll
                for (int cc = 0; cc < 12; cc++) {
                    const float w0 = scw[k * 72 + (c0 + cc) * 3 + 0];
                    const float w1 = scw[k * 72 + (c0 + cc) * 3 + 1];
                    const float w2 = scw[k * 72 + (c0 + cc) * 3 + 2];
#pragma unroll
                    for (int i = 0; i < 5; i++) {
                        acc[i] = fmaf(w0, xr[i][cc],     acc[i]);
                        acc[i] = fmaf(w1, xr[i + 1][cc], acc[i]);
                        acc[i] = fmaf(w2, xr[i + 2][cc], acc[i]);
                    }
                }
                if (ch == 0) {
#pragma unroll
                    for (int i = 0; i < 5; i++)
                        sCf[sp * SCST + k * SEQ + sq * 5 + i] = acc[i];
                } else {
#pragma unroll
                    for (int i = 0; i < 5; i++) {
                        const float v  = acc[i];
                        const float sg = fmaf(0.5f, tanhap(0.5f * v), 0.5f);
                        sC[sp * SCST + k * SEQ + sq * 5 + i] = f2tf(v * sg);
                    }
                }
            }
        }
    }
    __syncthreads();

    const int w    = tid >> 5;
    const int lane = tid & 31;
    const int g    = lane >> 2;
    const int tig  = lane & 3;
    const int mh   = w & 1;
    const int nq   = w >> 1;
    const int srow = mh * 16 + g;
    const int nbase = nq * 32;

    float c[4][4];
#pragma unroll
    for (int nt = 0; nt < 4; nt++) {
        const int n0 = nbase + nt * 8 + 2 * tig;
        c[nt][0] = __ldg(&enc1_b[n0]);
        c[nt][1] = __ldg(&enc1_b[n0 + 1]);
        c[nt][2] = c[nt][0];
        c[nt][3] = c[nt][1];
    }

    float4 pre[4];
#pragma unroll
    for (int j = 0; j < 4; j++) {
        const int f  = tid + j * 256;
        const int oc = f >> 3, qd = f & 7;
        pre[j] = __ldg((const float4*)(enc1_w + (size_t)oc * FLAT + qd * 4));
    }

    for (int kci = 0; kci < NCHUNK; kci++) {
        unsigned* buf = (kci & 1) ? sW1 : sW0;
#pragma unroll
        for (int j = 0; j < 4; j++) {
            const int f  = tid + j * 256;
            const int oc = f >> 3, qd = f & 7;
            uint4 u;
            u.x = f2tf(pre[j].x); u.y = f2tf(pre[j].y);
            u.z = f2tf(pre[j].z); u.w = f2tf(pre[j].w);
            *(uint4*)(buf + oc * SWST + qd * 4) = u;
        }
        if (kci + 1 < NCHUNK) {
            const int kc = (kci + 1) * 32;
#pragma unroll
            for (int j = 0; j < 4; j++) {
                const int f  = tid + j * 256;
                const int oc = f >> 3, qd = f & 7;
                pre[j] = __ldg((const float4*)(enc1_w + (size_t)oc * FLAT + kc + qd * 4));
            }
        }
        __syncthreads();
        const int kc = kci * 32;
#pragma unroll
        for (int kt = 0; kt < 4; kt++) {
            unsigned a[4];
            const unsigned* ar = sC + srow * SCST + kc + kt * 8 + tig;
            a[0] = ar[0];
            a[1] = ar[8 * SCST];
            a[2] = ar[4];
            a[3] = ar[8 * SCST + 4];
#pragma unroll
            for (int nt = 0; nt < 4; nt++) {
                const unsigned* br = buf + (nbase + nt * 8 + g) * SWST + kt * 8 + tig;
                mma_tf32(c[nt], a, br[0], br[4]);
            }
        }
    }
    __syncthreads();

#pragma unroll
    for (int nt = 0; nt < 4; nt++) {
        const int n0 = nbase + nt * 8 + 2 * tig;
        sH1[srow * SH1ST + n0]           = fmaxf(c[nt][0], 0.0f);
        sH1[srow * SH1ST + n0 + 1]       = fmaxf(c[nt][1], 0.0f);
        sH1[(srow + 8) * SH1ST + n0]     = fmaxf(c[nt][2], 0.0f);
        sH1[(srow + 8) * SH1ST + n0 + 1] = fmaxf(c[nt][3], 0.0f);
    }
    __syncthreads();

    for (int t = tid; t < ENC_SPB * HID; t += 256) {
        const int oc = t >> 5;
        const int sp = t & 31;
        float acc = __ldg(&enc2_b[oc]);
        const float* wr = enc2_w + oc * 128;
        const float* hv = sH1 + sp * SH1ST;
#pragma unroll
        for (int i = 0; i < 128; i += 4) {
            const float4 wv = __ldg((const float4*)(wr + i));
            const float4 h4 = *(const float4*)(hv + i);
            acc = fmaf(wv.x, h4.x, fmaf(wv.y, h4.y, fmaf(wv.z, h4.z, fmaf(wv.w, h4.w, acc))));
        }
        g_theta0[(size_t)oc * B + blk * ENC_SPB + sp] = acc;
    }
}

// ================================ ODE ======================================
// 16 samples/CTA, 128 threads = 4 warps (all share the one 16-sample block).
// fp16 m16n8k16; W1/W2 as A-fragments in regs (32 regs).  4 CTAs/SM.
#define ODE_SPB 16
#define KW 36

// c[nt] = bias + W * in   (in: fp16 pairs in SMEM, [16 samples][KW words])
__device__ __forceinline__ void gemm16h(
    const unsigned (&A)[4][4], const unsigned* __restrict__ sIn,
    float blo, float bhi, int g, int tig, float (&c)[2][4])
{
#pragma unroll
    for (int nt = 0; nt < 2; nt++) {
        c[nt][0] = blo; c[nt][1] = blo; c[nt][2] = bhi; c[nt][3] = bhi;
    }
#pragma unroll
    for (int kt = 0; kt < 4; kt++) {
#pragma unroll
        for (int nt = 0; nt < 2; nt++) {
            const unsigned* r = sIn + (nt * 8 + g) * KW + kt * 8 + tig;
            mma_fp16(c[nt], A[kt], r[0], r[4]);
        }
    }
}

// store C-frag (fp32) as fp16 into [n][k=m] layout
__device__ __forceinline__ void store_frag_h(
    unsigned* __restrict__ dst, const float (&c)[2][4], int m0, int tig)
{
    __half* d = (__half*)dst;
#pragma unroll
    for (int nt = 0; nt < 2; nt++) {
        const int n0 = nt * 8 + 2 * tig;
        d[(n0)     * (2*KW) + m0]     = __float2half_rn(c[nt][0]);
        d[(n0 + 1) * (2*KW) + m0]     = __float2half_rn(c[nt][1]);
        d[(n0)     * (2*KW) + m0 + 8] = __float2half_rn(c[nt][2]);
        d[(n0 + 1) * (2*KW) + m0 + 8] = __float2half_rn(c[nt][3]);
    }
}

// full f: sY -> k frags.  ONE internal barrier; caller barriers before reuse.
__device__ __forceinline__ void eval_fh(
    const unsigned (&A1)[4][4], const unsigned (&A2)[4][4],
    float b1lo, float b1hi, float b2lo, float b2hi,
    const unsigned* __restrict__ sY, unsigned* __restrict__ sH,
    int m0, int g, int tig, float (&k)[2][4])
{
    float h[2][4];
    gemm16h(A1, sY, b1lo, b1hi, g, tig, h);
#pragma unroll
    for (int nt = 0; nt < 2; nt++)
#pragma unroll
        for (int e = 0; e < 4; e++) h[nt][e] = tanhap(h[nt][e]);
    store_frag_h(sH, h, m0, tig);
    __syncthreads();     // all gemm1 sY reads done; sH complete
    gemm16h(A2, sH, b2lo, b2hi, g, tig, k);
}

__global__ void __launch_bounds__(128, 4) ode_kernel(
    const float* __restrict__ t_span,
    const float* __restrict__ w1g, const float* __restrict__ b1g,
    const float* __restrict__ w2g, const float* __restrict__ b2g,
    const float* __restrict__ r1w, const float* __restrict__ r1b,
    const float* __restrict__ r2w, const float* __restrict__ r2b,
    float* __restrict__ out, int B)
{
    __shared__ unsigned sODE[2 * ODE_SPB * KW];    // sY | sH (fp16 pairs)
    unsigned* sY = sODE;
    unsigned* sH = sODE + ODE_SPB * KW;

    const int tid  = threadIdx.x;
    const int w    = tid >> 5;                // warp = m-band
    const int lane = tid & 31;
    const int g    = lane >> 2;
    const int tig  = lane & 3;
    const int m0   = w * 16 + g;

    // ---- W1/W2 as fp16 A-fragments (m16n8k16) ----
    unsigned A1[4][4], A2[4][4];
#pragma unroll
    for (int kt = 0; kt < 4; kt++) {
        const int k0 = kt * 16 + 2 * tig;
        A1[kt][0] = pkh2(__ldg(&w1g[(m0)     * HID + k0]),     __ldg(&w1g[(m0)     * HID + k0 + 1]));
        A1[kt][1] = pkh2(__ldg(&w1g[(m0 + 8) * HID + k0]),     __ldg(&w1g[(m0 + 8) * HID + k0 + 1]));
        A1[kt][2] = pkh2(__ldg(&w1g[(m0)     * HID + k0 + 8]), __ldg(&w1g[(m0)     * HID + k0 + 9]));
        A1[kt][3] = pkh2(__ldg(&w1g[(m0 + 8) * HID + k0 + 8]), __ldg(&w1g[(m0 + 8) * HID + k0 + 9]));
        A2[kt][0] = pkh2(__ldg(&w2g[(m0)     * HID + k0]),     __ldg(&w2g[(m0)     * HID + k0 + 1]));
        A2[kt][1] = pkh2(__ldg(&w2g[(m0 + 8) * HID + k0]),     __ldg(&w2g[(m0 + 8) * HID + k0 + 1]));
        A2[kt][2] = pkh2(__ldg(&w2g[(m0)     * HID + k0 + 8]), __ldg(&w2g[(m0)     * HID + k0 + 9]));
        A2[kt][3] = pkh2(__ldg(&w2g[(m0 + 8) * HID + k0 + 8]), __ldg(&w2g[(m0 + 8) * HID + k0 + 9]));
    }
    const float b1lo = __ldg(&b1g[m0]), b1hi = __ldg(&b1g[m0 + 8]);
    const float b2lo = __ldg(&b2g[m0]), b2hi = __ldg(&b2g[m0 + 8]);

    const float dt = (__ldg(&t_span[1]) - __ldg(&t_span[0])) * (1.0f / STEPS);

    const long long gbase = (long long)blockIdx.x * ODE_SPB;
    float y[2][4];
#pragma unroll
    for (int nt = 0; nt < 2; nt++) {
        const long long n0 = gbase + nt * 8 + 2 * tig;
        y[nt][0] = __ldg(&g_theta0[(size_t)m0 * B + n0]);
        y[nt][1] = __ldg(&g_theta0[(size_t)m0 * B + n0 + 1]);
        y[nt][2] = __ldg(&g_theta0[(size_t)(m0 + 8) * B + n0]);
        y[nt][3] = __ldg(&g_theta0[(size_t)(m0 + 8) * B + n0 + 1]);
    }
    store_frag_h(sY, y, m0, tig);
    __syncthreads();

    float k1[2][4], k2[2][4], k3[2][4], k4[2][4], k5[2][4], k6[2][4], nv[2][4];

#define ELEM_LOOP(expr)                                                        \
    _Pragma("unroll") for (int nt = 0; nt < 2; nt++)                           \
    _Pragma("unroll") for (int e = 0; e < 4; e++) { expr; }

    for (int step = 0; step < STEPS; step++) {
        eval_fh(A1, A2, b1lo, b1hi, b2lo, b2hi, sY, sH, m0, g, tig, k1);
        {
            const float c1 = dt * 0.2f;
            ELEM_LOOP(nv[nt][e] = fmaf(c1, k1[nt][e], y[nt][e]));
            store_frag_h(sY, nv, m0, tig);
        }
        __syncthreads();
        eval_fh(A1, A2, b1lo, b1hi, b2lo, b2hi, sY, sH, m0, g, tig, k2);
        {
            const float c1 = dt * (3.0f / 40.0f), c2 = dt * (9.0f / 40.0f);
            ELEM_LOOP(nv[nt][e] = fmaf(c1, k1[nt][e], fmaf(c2, k2[nt][e], y[nt][e])));
            store_frag_h(sY, nv, m0, tig);
        }
        __syncthreads();
        eval_fh(A1, A2, b1lo, b1hi, b2lo, b2hi, sY, sH, m0, g, tig, k3);
        {
            const float c1 = dt * (44.0f / 45.0f), c2 = dt * (-56.0f / 15.0f),
                        c3 = dt * (32.0f / 9.0f);
            ELEM_LOOP(nv[nt][e] = fmaf(c1, k1[nt][e], fmaf(c2, k2[nt][e],
                                  fmaf(c3, k3[nt][e], y[nt][e]))));
            store_frag_h(sY, nv, m0, tig);
        }
        __syncthreads();
        eval_fh(A1, A2, b1lo, b1hi, b2lo, b2hi, sY, sH, m0, g, tig, k4);
        {
            const float c1 = dt * (19372.0f / 6561.0f), c2 = dt * (-25360.0f / 2187.0f),
                        c3 = dt * (64448.0f / 6561.0f), c4 = dt * (-212.0f / 729.0f);
            ELEM_LOOP(nv[nt][e] = fmaf(c1, k1[nt][e], fmaf(c2, k2[nt][e],
                                  fmaf(c3, k3[nt][e], fmaf(c4, k4[nt][e], y[nt][e])))));
            store_frag_h(sY, nv, m0, tig);
        }
        __syncthreads();
        eval_fh(A1, A2, b1lo, b1hi, b2lo, b2hi, sY, sH, m0, g, tig, k5);
        {
            const float c1 = dt * (9017.0f / 3168.0f), c2 = dt * (-355.0f / 33.0f),
                        c3 = dt * (46732.0f / 5247.0f), c4 = dt * (49.0f / 176.0f),
                        c5 = dt * (-5103.0f / 18656.0f);
            ELEM_LOOP(nv[nt][e] = fmaf(c1, k1[nt][e], fmaf(c2, k2[nt][e],
                                  fmaf(c3, k3[nt][e], fmaf(c4, k4[nt][e],
                                  fmaf(c5, k5[nt][e], y[nt][e]))))));
            store_frag_h(sY, nv, m0, tig);
        }
        __syncthreads();
        eval_fh(A1, A2, b1lo, b1hi, b2lo, b2hi, sY, sH, m0, g, tig, k6);
        {
            const float c1 = dt * (35.0f / 384.0f),  c3 = dt * (500.0f / 1113.0f),
                        c4 = dt * (125.0f / 192.0f), c5 = dt * (-2187.0f / 6784.0f),
                        c6 = dt * (11.0f / 84.0f);
            ELEM_LOOP(y[nt][e] = fmaf(c1, k1[nt][e], fmaf(c3, k3[nt][e],
                                 fmaf(c4, k4[nt][e], fmaf(c5, k5[nt][e],
                                 fmaf(c6, k6[nt][e], y[nt][e]))))));
            store_frag_h(sY, y, m0, tig);
        }
        __syncthreads();
    }

    // ---- write final y (fp32) into [sample][dim] layout over sODE ----
    {
        float* sYf = (float*)sODE;                 // [16][68] floats (4352 B)
#pragma unroll
        for (int nt = 0; nt < 2; nt++) {
            const int n0 = nt * 8 + 2 * tig;
            sYf[(n0)     * 68 + m0]     = y[nt][0];
            sYf[(n0 + 1) * 68 + m0]     = y[nt][1];
            sYf[(n0)     * 68 + m0 + 8] = y[nt][2];
            sYf[(n0 + 1) * 68 + m0 + 8] = y[nt][3];
        }
    }
    __syncthreads();

    // ---- regressor: 8 threads per sample, 4 reg1 rows each ----
    {
        const float* sYf = (const float*)sODE;
        const int s  = tid >> 3;                 // 0..15
        const int mg = (tid & 7) * 4;
        float accm[4];
#pragma unroll
        for (int m = 0; m < 4; m++) accm[m] = __ldg(&r1b[mg + m]);
        for (int i = 0; i < HID; i++) {
            const float yy = sYf[s * 68 + i];
#pragma unroll
            for (int m = 0; m < 4; m++)
                accm[m] = fmaf(__ldg(&r1w[(mg + m) * HID + i]), yy, accm[m]);
        }
        float part = 0.0f;
#pragma unroll
        for (int m = 0; m < 4; m++)
            part = fmaf(__ldg(&r2w[mg + m]), fmaxf(accm[m], 0.0f), part);
        part += __shfl_xor_sync(0xffffffffu, part, 1);
        part += __shfl_xor_sync(0xffffffffu, part, 2);
        part += __shfl_xor_sync(0xffffffffu, part, 4);
        if ((tid & 7) == 0)
            out[(long long)blockIdx.x * ODE_SPB + s] = part + __ldg(&r2b[0]);
    }
}

// ============================== launch ======================================
extern "C" void kernel_launch(void* const* d_in, const int* in_sizes, int n_in,
                              void* d_out, int out_size)
{
    const float* x      = (const float*)d_in[0];
    const float* t_span = (const float*)d_in[1];
    const float* conv_w = (const float*)d_in[2];
    const float* conv_b = (const float*)d_in[3];
    const float* enc1_w = (const float*)d_in[4];
    const float* enc1_b = (const float*)d_in[5];
    const float* enc2_w = (const float*)d_in[6];
    const float* enc2_b = (const float*)d_in[7];
    const float* ode1_w = (const float*)d_in[8];
    const float* ode1_b = (const float*)d_in[9];
    const float* ode2_w = (const float*)d_in[10];
    const float* ode2_b = (const float*)d_in[11];
    const float* reg1_w = (const float*)d_in[12];
    const float* reg1_b = (const float*)d_in[13];
    const float* reg2_w = (const float*)d_in[14];
    const float* reg2_b = (const float*)d_in[15];
    float* out = (float*)d_out;

    const int B = in_sizes[0] / (SEQ * INC);

    cudaFuncSetAttribute(enc_kernel, cudaFuncAttributeMaxDynamicSharedMemorySize,
                         ENC_SMEM_BYTES);

    enc_kernel<<<B / ENC_SPB, 256, ENC_SMEM_BYTES>>>(
        x, conv_w, conv_b, enc1_w, enc1_b, enc2_w, enc2_b, B);
    ode_kernel<<<B / ODE_SPB, 128>>>(
        t_span, ode1_w, ode1_b, ode2_w, ode2_b,
        reg1_w, reg1_b, reg2_w, reg2_b, out, B);
}